// round 4
// baseline (speedup 1.0000x reference)
#include <cuda_runtime.h>
#include <cuda_bf16.h>
#include <mma.h>
#include <cstdint>
#include <cstddef>

using namespace nvcuda;
typedef __nv_bfloat16 bf16;

#define BATCH 4
#define CQd   256
#define NQd   2048
#define NKVd  2048
#define NH    8
#define DKd   64
#define ODd   512   // NH*DKd

// ---------------- scratch (static device globals; no runtime alloc) -------
__device__ __align__(16) bf16 g_xq [BATCH*CQd*NQd];
__device__ __align__(16) bf16 g_xkv[BATCH*CQd*NKVd];
__device__ __align__(16) bf16 g_Wq [ODd*CQd];
__device__ __align__(16) bf16 g_Wk [ODd*CQd];
__device__ __align__(16) bf16 g_Wv [ODd*CQd];
__device__ __align__(16) bf16 g_Wo [CQd*ODd];
__device__ __align__(16) bf16 g_Q  [BATCH*ODd*NQd];
__device__ __align__(16) bf16 g_K  [BATCH*ODd*NKVd];
__device__ __align__(16) bf16 g_V  [BATCH*ODd*NKVd];
__device__ __align__(16) bf16 g_Wp [BATCH*CQd*ODd];   // fused Wo @ blockdiag(M^T)

// ---------------- fused fp32 -> bf16 conversion (all 6 tensors) -----------
__global__ void convert_all_kernel(const float* __restrict__ xq,
                                   const float* __restrict__ xkv,
                                   const float* __restrict__ Wq,
                                   const float* __restrict__ Wk,
                                   const float* __restrict__ Wv,
                                   const float* __restrict__ Wo) {
    int i = blockIdx.x * blockDim.x + threadIdx.x;  // float4 index, total 1179648
    const float* src; bf16* dst; int off;
    if (i < 524288)            { src = xq;  dst = g_xq;  off = i; }
    else if (i < 1048576)      { src = xkv; dst = g_xkv; off = i - 524288; }
    else {
        int j = i - 1048576;
        int w = j >> 15;  off = j & 32767;
        src = (w == 0) ? Wq : (w == 1) ? Wk : (w == 2) ? Wv : Wo;
        dst = (w == 0) ? g_Wq : (w == 1) ? g_Wk : (w == 2) ? g_Wv : g_Wo;
    }
    float4 v = ((const float4*)src)[off];
    __nv_bfloat162 two[2] = { __floats2bfloat162_rn(v.x, v.y),
                              __floats2bfloat162_rn(v.z, v.w) };
    *(uint2*)&dst[(size_t)off * 4] = *(uint2*)two;
}

// ---------------- cp.async helpers -----------------------------------------
__device__ __forceinline__ void cpa16(void* dst, const void* src) {
    unsigned int d = (unsigned int)__cvta_generic_to_shared(dst);
    asm volatile("cp.async.cg.shared.global [%0], [%1], 16;\n" :: "r"(d), "l"(src));
}
__device__ __forceinline__ void cpa_commit() {
    asm volatile("cp.async.commit_group;\n" ::);
}

// ---------------- pipelined 128x128x64 bf16 GEMM core ----------------------
// Y(OxN) = W(OxCD) * X(CDxN).  FINAL: Yf = gamma*acc + resid (fp32), else bf16.
// 256 threads, 8 warps (2x4), warp tile 64x32, double-buffered cp.async,
// K-stage = 64.
template<int CD>
__device__ __forceinline__ void stage_tiles(const bf16* __restrict__ W,
                                            const bf16* __restrict__ Xb,
                                            bf16* As, bf16* Bs,
                                            int o0, int n0, int k0, int tid) {
    #pragma unroll
    for (int u = 0; u < 4; u++) {             // A: 128x64, 1024 16B chunks
        int ch = tid + u * 256;
        int r = ch >> 3, cc = (ch & 7) * 8;
        cpa16(As + r * 72 + cc, W + (size_t)(o0 + r) * CD + k0 + cc);
    }
    #pragma unroll
    for (int u = 0; u < 4; u++) {             // B: 64x128, 1024 16B chunks
        int ch = tid + u * 256;
        int r = ch >> 4, cc = (ch & 15) * 8;
        cpa16(Bs + r * 136 + cc, Xb + (size_t)(k0 + r) * NQd + n0 + cc);
    }
    cpa_commit();
}

template<bool FINAL, int CD>
__device__ __forceinline__ void gemm_core(const bf16* __restrict__ W,
                                          const bf16* __restrict__ Xb,
                                          bf16* __restrict__ Ybf,
                                          float* __restrict__ Yf,
                                          const float* __restrict__ resid,
                                          const float* __restrict__ gammap) {
    const int n0 = blockIdx.x * 128;
    const int o0 = blockIdx.y * 128;
    extern __shared__ __align__(16) char smem_raw[];
    bf16*  AsB = (bf16*)smem_raw;              // [2][128*72]  = 36864 B
    bf16*  BsB = (bf16*)(smem_raw + 36864);    // [2][64*136]  = 34816 B
    float* Cs  = (float*)smem_raw;             // [128*132]    = 67584 B (reuse)

    const int tid  = threadIdx.x;
    const int warp = tid >> 5;
    const int wr   = warp >> 2;   // 0..1 (64-row half)
    const int wc   = warp & 3;    // 0..3 (32-col quarter)

    wmma::fragment<wmma::accumulator,16,16,16,float> acc[4][2];
    #pragma unroll
    for (int i = 0; i < 4; i++)
        #pragma unroll
        for (int j = 0; j < 2; j++) wmma::fill_fragment(acc[i][j], 0.0f);

    constexpr int KT = CD / 64;
    stage_tiles<CD>(W, Xb, AsB, BsB, o0, n0, 0, tid);

    for (int kt = 0; kt < KT; kt++) {
        if (kt + 1 < KT) {
            stage_tiles<CD>(W, Xb, AsB + ((kt + 1) & 1) * 128 * 72,
                                    BsB + ((kt + 1) & 1) * 64 * 136,
                            o0, n0, (kt + 1) * 64, tid);
            asm volatile("cp.async.wait_group 1;\n" ::);
        } else {
            asm volatile("cp.async.wait_group 0;\n" ::);
        }
        __syncthreads();

        const bf16* As = AsB + (kt & 1) * 128 * 72;
        const bf16* Bs = BsB + (kt & 1) * 64 * 136;
        #pragma unroll
        for (int ks = 0; ks < 4; ks++) {
            wmma::fragment<wmma::matrix_a,16,16,16,bf16,wmma::row_major> af[4];
            wmma::fragment<wmma::matrix_b,16,16,16,bf16,wmma::row_major> bg[2];
            #pragma unroll
            for (int i = 0; i < 4; i++)
                wmma::load_matrix_sync(af[i], As + (wr*64 + i*16) * 72 + ks*16, 72);
            #pragma unroll
            for (int j = 0; j < 2; j++)
                wmma::load_matrix_sync(bg[j], Bs + (ks*16) * 136 + wc*32 + j*16, 136);
            #pragma unroll
            for (int i = 0; i < 4; i++)
                #pragma unroll
                for (int j = 0; j < 2; j++)
                    wmma::mma_sync(acc[i][j], af[i], bg[j], acc[i][j]);
        }
        __syncthreads();
    }

    // epilogue via Cs (smem reuse is safe: accum is in registers)
    #pragma unroll
    for (int i = 0; i < 4; i++)
        #pragma unroll
        for (int j = 0; j < 2; j++)
            wmma::store_matrix_sync(&Cs[(wr*64 + i*16) * 132 + wc*32 + j*16],
                                    acc[i][j], 132, wmma::mem_row_major);
    __syncthreads();

    float g = 0.0f;
    if (FINAL) g = gammap[0];
    #pragma unroll
    for (int t = tid; t < 4096; t += 256) {    // 128x128 / 4-wide
        int r = t >> 5, c4 = (t & 31) * 4;
        float4 v = *(float4*)&Cs[r * 132 + c4];
        size_t gi = (size_t)(o0 + r) * NQd + n0 + c4;
        if (FINAL) {
            float4 x = *(const float4*)&resid[gi];
            v.x = g * v.x + x.x;  v.y = g * v.y + x.y;
            v.z = g * v.z + x.z;  v.w = g * v.w + x.w;
            *(float4*)&Yf[gi] = v;
        } else {
            __nv_bfloat162 two[2] = { __floats2bfloat162_rn(v.x, v.y),
                                      __floats2bfloat162_rn(v.z, v.w) };
            *(uint2*)&Ybf[gi] = *(uint2*)two;
        }
    }
}

// ---------------- Q/K/V projections: one launch, z = b*3 + which -----------
struct ProjArgs { const bf16* W[3]; const bf16* X[2]; bf16* Y[3]; };

__global__ void proj_kernel(ProjArgs a) {
    int z = blockIdx.z;
    int which = z % 3, b = z / 3;
    const bf16* W  = a.W[which];
    const bf16* Xb = (which == 0 ? a.X[0] : a.X[1]) + (size_t)b * CQd * NQd;
    bf16*       Yb = a.Y[which] + (size_t)b * ODd * NQd;
    gemm_core<false, CQd>(W, Xb, Yb, nullptr, nullptr, nullptr);
}

// ---------------- final: out = gamma * (W'_b @ Q_b) + x_q ------------------
__global__ void final_kernel(const float* __restrict__ xq,
                             const float* __restrict__ gammap,
                             float* __restrict__ out) {
    int b = blockIdx.z;
    gemm_core<true, ODd>(g_Wp + (size_t)b * CQd * ODd,
                         g_Q  + (size_t)b * ODd * NQd,
                         nullptr,
                         out + (size_t)b * CQd * NQd,
                         xq  + (size_t)b * CQd * NQd,
                         gammap);
}

// ---------------- fused: M = (K^T V)/dk, then Wp(:,h) = Wo(:,h) @ M~^T -----
// grid (NH, BATCH), 256 threads. M~ never leaves the SM.
// smem layout: Cs f32 [256][68] at 0 (69632 B, phase-1 partials Ms overlap it),
//              Msh bf16 [64][72] at 69632 (9216 B). total 78848 B.
__global__ void kvfuse_kernel() {
    const int h = blockIdx.x, b = blockIdx.y;
    const bf16* Kb = g_K + ((size_t)b * ODd + h * DKd) * NKVd;
    const bf16* Vb = g_V + ((size_t)b * ODd + h * DKd) * NKVd;

    extern __shared__ __align__(16) char smem_raw[];
    float* Cs  = (float*)smem_raw;                    // [256][68]
    float* Ms  = (float*)smem_raw;                    // [2][64][68] (overlap)
    bf16*  Msh = (bf16*)(smem_raw + 69632);           // [64][72]

    const int tid  = threadIdx.x;
    const int warp = tid >> 5;
    const int kg   = warp >> 2;       // K half: 0 or 1
    const int quad = warp & 3;
    const int qr   = quad >> 1, qc = quad & 1;

    // ---- phase 1: M_part[kg] = K[qr-rows] * V[qc-rows]^T over K half ----
    {
        wmma::fragment<wmma::accumulator,16,16,16,float> acc[2][2];
        #pragma unroll
        for (int i = 0; i < 2; i++)
            #pragma unroll
            for (int j = 0; j < 2; j++) wmma::fill_fragment(acc[i][j], 0.0f);

        const int k0 = kg * (NKVd / 2);
        for (int k = k0; k < k0 + NKVd / 2; k += 16) {
            wmma::fragment<wmma::matrix_a,16,16,16,bf16,wmma::row_major> af[2];
            wmma::fragment<wmma::matrix_b,16,16,16,bf16,wmma::col_major> bg[2];
            #pragma unroll
            for (int i = 0; i < 2; i++)
                wmma::load_matrix_sync(af[i], Kb + (size_t)(qr*32 + i*16) * NKVd + k, NKVd);
            #pragma unroll
            for (int j = 0; j < 2; j++)
                wmma::load_matrix_sync(bg[j], Vb + (size_t)(qc*32 + j*16) * NKVd + k, NKVd);
            #pragma unroll
            for (int i = 0; i < 2; i++)
                #pragma unroll
                for (int j = 0; j < 2; j++)
                    wmma::mma_sync(acc[i][j], af[i], bg[j], acc[i][j]);
        }
        #pragma unroll
        for (int i = 0; i < 2; i++)
            #pragma unroll
            for (int j = 0; j < 2; j++)
                wmma::store_matrix_sync(Ms + (size_t)kg * 64 * 68
                                           + (qr*32 + i*16) * 68 + qc*32 + j*16,
                                        acc[i][j], 68, wmma::mem_row_major);
    }
    __syncthreads();

    // ---- reduce the two K-halves, scale by 1/64, convert to bf16 ----
    #pragma unroll
    for (int t = tid; t < 4096; t += 256) {
        int r = t >> 6, c = t & 63;
        float s = Ms[r * 68 + c] + Ms[64 * 68 + r * 68 + c];
        Msh[r * 72 + c] = __float2bfloat16(s * (1.0f / DKd));
    }
    __syncthreads();

    // ---- phase 2: Wp[c, h*64+d] = sum_e Wo[c, h*64+e] * M~[d, e] ----
    // warp owns c-rows [warp*32, warp*32+32); acc 2x4 frags (32 x 64)
    {
        wmma::fragment<wmma::accumulator,16,16,16,float> acc[2][4];
        #pragma unroll
        for (int i = 0; i < 2; i++)
            #pragma unroll
            for (int j = 0; j < 4; j++) wmma::fill_fragment(acc[i][j], 0.0f);

        #pragma unroll
        for (int kt = 0; kt < 4; kt++) {     // e blocks
            wmma::fragment<wmma::matrix_a,16,16,16,bf16,wmma::row_major> af[2];
            wmma::fragment<wmma::matrix_b,16,16,16,bf16,wmma::col_major> bg[4];
            #pragma unroll
            for (int i = 0; i < 2; i++)
                wmma::load_matrix_sync(af[i],
                    g_Wo + (size_t)(warp*32 + i*16) * ODd + h * DKd + kt*16, ODd);
            #pragma unroll
            for (int j = 0; j < 4; j++)   // B(e,d) = M~[d,e] -> col_major ldm 72
                wmma::load_matrix_sync(bg[j], Msh + (j*16) * 72 + kt*16, 72);
            #pragma unroll
            for (int i = 0; i < 2; i++)
                #pragma unroll
                for (int j = 0; j < 4; j++)
                    wmma::mma_sync(acc[i][j], af[i], bg[j], acc[i][j]);
        }
        #pragma unroll
        for (int i = 0; i < 2; i++)
            #pragma unroll
            for (int j = 0; j < 4; j++)
                wmma::store_matrix_sync(Cs + (size_t)(warp*32 + i*16) * 68 + j*16,
                                        acc[i][j], 68, wmma::mem_row_major);
    }
    __syncthreads();

    // ---- write Wp slice (256 x 64 bf16) ----
    bf16* Wpb = g_Wp + (size_t)b * CQd * ODd;
    #pragma unroll
    for (int t = tid; t < 4096; t += 256) {
        int r = t >> 4, c4 = (t & 15) * 4;
        float4 v = *(float4*)&Cs[r * 68 + c4];
        __nv_bfloat162 two[2] = { __floats2bfloat162_rn(v.x, v.y),
                                  __floats2bfloat162_rn(v.z, v.w) };
        *(uint2*)&Wpb[(size_t)r * ODd + h * DKd + c4] = *(uint2*)two;
    }
}

// ---------------------------------------------------------------------------
extern "C" void kernel_launch(void* const* d_in, const int* in_sizes, int n_in,
                              void* d_out, int out_size) {
    const float* xq    = (const float*)d_in[0];
    const float* xkv   = (const float*)d_in[1];
    const float* Wq    = (const float*)d_in[2];
    const float* Wk    = (const float*)d_in[3];
    const float* Wv    = (const float*)d_in[4];
    const float* Wo    = (const float*)d_in[5];
    const float* gamma = (const float*)d_in[6];
    float* out = (float*)d_out;

    cudaFuncSetAttribute(proj_kernel,   cudaFuncAttributeMaxDynamicSharedMemorySize, 71680);
    cudaFuncSetAttribute(final_kernel,  cudaFuncAttributeMaxDynamicSharedMemorySize, 71680);
    cudaFuncSetAttribute(kvfuse_kernel, cudaFuncAttributeMaxDynamicSharedMemorySize, 78848);

    // 1) convert everything to bf16 (one launch)
    convert_all_kernel<<<4608, 256>>>(xq, xkv, Wq, Wk, Wv, Wo);

    // 2) Q/K/V projections (one launch, z = b*3 + which)
    ProjArgs pa;
    void *p;
    cudaGetSymbolAddress(&p, g_Wq);  pa.W[0] = (const bf16*)p;
    cudaGetSymbolAddress(&p, g_Wk);  pa.W[1] = (const bf16*)p;
    cudaGetSymbolAddress(&p, g_Wv);  pa.W[2] = (const bf16*)p;
    cudaGetSymbolAddress(&p, g_xq);  pa.X[0] = (const bf16*)p;
    cudaGetSymbolAddress(&p, g_xkv); pa.X[1] = (const bf16*)p;
    cudaGetSymbolAddress(&p, g_Q);   pa.Y[0] = (bf16*)p;
    cudaGetSymbolAddress(&p, g_K);   pa.Y[1] = (bf16*)p;
    cudaGetSymbolAddress(&p, g_V);   pa.Y[2] = (bf16*)p;
    proj_kernel<<<dim3(NQd/128, ODd/128, BATCH*3), 256, 71680>>>(pa);

    // 3) fused M = (K^T V)/dk  +  Wp = Wo @ blockdiag(M^T)
    kvfuse_kernel<<<dim3(NH, BATCH), 256, 78848>>>();

    // 4) out = gamma * (Wp_b @ Q_b) + x_q
    final_kernel<<<dim3(NQd/128, CQd/128, BATCH), 256, 71680>>>(xq, gamma, out);
}

// round 5
// speedup vs baseline: 1.0062x; 1.0062x over previous
#include <cuda_runtime.h>
#include <cuda_bf16.h>
#include <mma.h>
#include <cstdint>
#include <cstddef>

using namespace nvcuda;
typedef __nv_bfloat16 bf16;

#define BATCH 4
#define CQd   256
#define NQd   2048
#define NKVd  2048
#define NH    8
#define DKd   64
#define ODd   512   // NH*DKd

// ---------------- scratch (static device globals; no runtime alloc) -------
__device__ __align__(16) bf16 g_xq [BATCH*CQd*NQd];
__device__ __align__(16) bf16 g_xkv[BATCH*CQd*NKVd];
__device__ __align__(16) bf16 g_Wq [ODd*CQd];
__device__ __align__(16) bf16 g_Wk [ODd*CQd];
__device__ __align__(16) bf16 g_Wv [ODd*CQd];
__device__ __align__(16) bf16 g_Wo [CQd*ODd];
__device__ __align__(16) bf16 g_Q  [BATCH*ODd*NQd];
__device__ __align__(16) bf16 g_K  [BATCH*ODd*NKVd];
__device__ __align__(16) bf16 g_V  [BATCH*ODd*NKVd];
__device__ __align__(16) bf16 g_Wp [BATCH*CQd*ODd];   // fused Wo @ blockdiag(M^T)

// ---------------- fused fp32 -> bf16 conversion (all 6 tensors) -----------
__global__ void convert_all_kernel(const float* __restrict__ xq,
                                   const float* __restrict__ xkv,
                                   const float* __restrict__ Wq,
                                   const float* __restrict__ Wk,
                                   const float* __restrict__ Wv,
                                   const float* __restrict__ Wo) {
    int i = blockIdx.x * blockDim.x + threadIdx.x;  // float4 index, total 1179648
    const float* src; bf16* dst; int off;
    if (i < 524288)            { src = xq;  dst = g_xq;  off = i; }
    else if (i < 1048576)      { src = xkv; dst = g_xkv; off = i - 524288; }
    else {
        int j = i - 1048576;
        int w = j >> 15;  off = j & 32767;
        src = (w == 0) ? Wq : (w == 1) ? Wk : (w == 2) ? Wv : Wo;
        dst = (w == 0) ? g_Wq : (w == 1) ? g_Wk : (w == 2) ? g_Wv : g_Wo;
    }
    float4 v = ((const float4*)src)[off];
    __nv_bfloat162 two[2] = { __floats2bfloat162_rn(v.x, v.y),
                              __floats2bfloat162_rn(v.z, v.w) };
    *(uint2*)&dst[(size_t)off * 4] = *(uint2*)two;
}

// ---------------- cp.async helpers -----------------------------------------
__device__ __forceinline__ void cpa16(void* dst, const void* src) {
    unsigned int d = (unsigned int)__cvta_generic_to_shared(dst);
    asm volatile("cp.async.cg.shared.global [%0], [%1], 16;\n" :: "r"(d), "l"(src));
}
__device__ __forceinline__ void cpa_commit() {
    asm volatile("cp.async.commit_group;\n" ::);
}

// ---------------- pipelined 128x128x64 bf16 GEMM core ----------------------
// Y(OxN) = W(OxCD) * X(CDxN).  FINAL: Yf = gamma*acc + resid (fp32), else bf16.
// 256 threads, 8 warps (2x4), warp tile 64x32, double-buffered cp.async,
// K-stage = 64.
template<int CD>
__device__ __forceinline__ void stage_tiles(const bf16* __restrict__ W,
                                            const bf16* __restrict__ Xb,
                                            bf16* As, bf16* Bs,
                                            int o0, int n0, int k0, int tid) {
    #pragma unroll
    for (int u = 0; u < 4; u++) {             // A: 128x64, 1024 16B chunks
        int ch = tid + u * 256;
        int r = ch >> 3, cc = (ch & 7) * 8;
        cpa16(As + r * 72 + cc, W + (size_t)(o0 + r) * CD + k0 + cc);
    }
    #pragma unroll
    for (int u = 0; u < 4; u++) {             // B: 64x128, 1024 16B chunks
        int ch = tid + u * 256;
        int r = ch >> 4, cc = (ch & 15) * 8;
        cpa16(Bs + r * 136 + cc, Xb + (size_t)(k0 + r) * NQd + n0 + cc);
    }
    cpa_commit();
}

template<bool FINAL, int CD>
__device__ __forceinline__ void gemm_core(const bf16* __restrict__ W,
                                          const bf16* __restrict__ Xb,
                                          bf16* __restrict__ Ybf,
                                          float* __restrict__ Yf,
                                          const float* __restrict__ resid,
                                          const float* __restrict__ gammap) {
    const int n0 = blockIdx.x * 128;
    const int o0 = blockIdx.y * 128;
    extern __shared__ __align__(16) char smem_raw[];
    bf16*  AsB = (bf16*)smem_raw;              // [2][128*72]  = 36864 B
    bf16*  BsB = (bf16*)(smem_raw + 36864);    // [2][64*136]  = 34816 B
    float* Cs  = (float*)smem_raw;             // [128*132]    = 67584 B (reuse)

    const int tid  = threadIdx.x;
    const int warp = tid >> 5;
    const int wr   = warp >> 2;   // 0..1 (64-row half)
    const int wc   = warp & 3;    // 0..3 (32-col quarter)

    wmma::fragment<wmma::accumulator,16,16,16,float> acc[4][2];
    #pragma unroll
    for (int i = 0; i < 4; i++)
        #pragma unroll
        for (int j = 0; j < 2; j++) wmma::fill_fragment(acc[i][j], 0.0f);

    constexpr int KT = CD / 64;
    stage_tiles<CD>(W, Xb, AsB, BsB, o0, n0, 0, tid);

    for (int kt = 0; kt < KT; kt++) {
        if (kt + 1 < KT) {
            stage_tiles<CD>(W, Xb, AsB + ((kt + 1) & 1) * 128 * 72,
                                    BsB + ((kt + 1) & 1) * 64 * 136,
                            o0, n0, (kt + 1) * 64, tid);
            asm volatile("cp.async.wait_group 1;\n" ::);
        } else {
            asm volatile("cp.async.wait_group 0;\n" ::);
        }
        __syncthreads();

        const bf16* As = AsB + (kt & 1) * 128 * 72;
        const bf16* Bs = BsB + (kt & 1) * 64 * 136;
        #pragma unroll
        for (int ks = 0; ks < 4; ks++) {
            wmma::fragment<wmma::matrix_a,16,16,16,bf16,wmma::row_major> af[4];
            wmma::fragment<wmma::matrix_b,16,16,16,bf16,wmma::row_major> bg[2];
            #pragma unroll
            for (int i = 0; i < 4; i++)
                wmma::load_matrix_sync(af[i], As + (wr*64 + i*16) * 72 + ks*16, 72);
            #pragma unroll
            for (int j = 0; j < 2; j++)
                wmma::load_matrix_sync(bg[j], Bs + (ks*16) * 136 + wc*32 + j*16, 136);
            #pragma unroll
            for (int i = 0; i < 4; i++)
                #pragma unroll
                for (int j = 0; j < 2; j++)
                    wmma::mma_sync(acc[i][j], af[i], bg[j], acc[i][j]);
        }
        __syncthreads();
    }

    // epilogue via Cs (smem reuse is safe: accum is in registers)
    #pragma unroll
    for (int i = 0; i < 4; i++)
        #pragma unroll
        for (int j = 0; j < 2; j++)
            wmma::store_matrix_sync(&Cs[(wr*64 + i*16) * 132 + wc*32 + j*16],
                                    acc[i][j], 132, wmma::mem_row_major);
    __syncthreads();

    float g = 0.0f;
    if (FINAL) g = gammap[0];
    #pragma unroll
    for (int t = tid; t < 4096; t += 256) {    // 128x128 / 4-wide
        int r = t >> 5, c4 = (t & 31) * 4;
        float4 v = *(float4*)&Cs[r * 132 + c4];
        size_t gi = (size_t)(o0 + r) * NQd + n0 + c4;
        if (FINAL) {
            float4 x = *(const float4*)&resid[gi];
            v.x = g * v.x + x.x;  v.y = g * v.y + x.y;
            v.z = g * v.z + x.z;  v.w = g * v.w + x.w;
            *(float4*)&Yf[gi] = v;
        } else {
            __nv_bfloat162 two[2] = { __floats2bfloat162_rn(v.x, v.y),
                                      __floats2bfloat162_rn(v.z, v.w) };
            *(uint2*)&Ybf[gi] = *(uint2*)two;
        }
    }
}

// ---------------- Q/K/V projections: one launch, z = b*3 + which -----------
struct ProjArgs { const bf16* W[3]; const bf16* X[2]; bf16* Y[3]; };

__global__ void proj_kernel(ProjArgs a) {
    int z = blockIdx.z;
    int which = z % 3, b = z / 3;
    const bf16* W  = a.W[which];
    const bf16* Xb = (which == 0 ? a.X[0] : a.X[1]) + (size_t)b * CQd * NQd;
    bf16*       Yb = a.Y[which] + (size_t)b * ODd * NQd;
    gemm_core<false, CQd>(W, Xb, Yb, nullptr, nullptr, nullptr);
}

// ---------------- final: out = gamma * (W'_b @ Q_b) + x_q ------------------
__global__ void final_kernel(const float* __restrict__ xq,
                             const float* __restrict__ gammap,
                             float* __restrict__ out) {
    int b = blockIdx.z;
    gemm_core<true, ODd>(g_Wp + (size_t)b * CQd * ODd,
                         g_Q  + (size_t)b * ODd * NQd,
                         nullptr,
                         out + (size_t)b * CQd * NQd,
                         xq  + (size_t)b * CQd * NQd,
                         gammap);
}

// ---------------- fused: M = (K^T V)/dk, then Wp(:,h) = Wo(:,h) @ M~^T -----
// grid (NH, BATCH), 256 threads. M~ never leaves the SM.
// smem layout: Cs f32 [256][68] at 0 (69632 B, phase-1 partials Ms overlap it),
//              Msh bf16 [64][72] at 69632 (9216 B). total 78848 B.
__global__ void kvfuse_kernel() {
    const int h = blockIdx.x, b = blockIdx.y;
    const bf16* Kb = g_K + ((size_t)b * ODd + h * DKd) * NKVd;
    const bf16* Vb = g_V + ((size_t)b * ODd + h * DKd) * NKVd;

    extern __shared__ __align__(16) char smem_raw[];
    float* Cs  = (float*)smem_raw;                    // [256][68]
    float* Ms  = (float*)smem_raw;                    // [2][64][68] (overlap)
    bf16*  Msh = (bf16*)(smem_raw + 69632);           // [64][72]

    const int tid  = threadIdx.x;
    const int warp = tid >> 5;
    const int kg   = warp >> 2;       // K half: 0 or 1
    const int quad = warp & 3;
    const int qr   = quad >> 1, qc = quad & 1;

    // ---- phase 1: M_part[kg] = K[qr-rows] * V[qc-rows]^T over K half ----
    {
        wmma::fragment<wmma::accumulator,16,16,16,float> acc[2][2];
        #pragma unroll
        for (int i = 0; i < 2; i++)
            #pragma unroll
            for (int j = 0; j < 2; j++) wmma::fill_fragment(acc[i][j], 0.0f);

        const int k0 = kg * (NKVd / 2);
        for (int k = k0; k < k0 + NKVd / 2; k += 16) {
            wmma::fragment<wmma::matrix_a,16,16,16,bf16,wmma::row_major> af[2];
            wmma::fragment<wmma::matrix_b,16,16,16,bf16,wmma::col_major> bg[2];
            #pragma unroll
            for (int i = 0; i < 2; i++)
                wmma::load_matrix_sync(af[i], Kb + (size_t)(qr*32 + i*16) * NKVd + k, NKVd);
            #pragma unroll
            for (int j = 0; j < 2; j++)
                wmma::load_matrix_sync(bg[j], Vb + (size_t)(qc*32 + j*16) * NKVd + k, NKVd);
            #pragma unroll
            for (int i = 0; i < 2; i++)
                #pragma unroll
                for (int j = 0; j < 2; j++)
                    wmma::mma_sync(acc[i][j], af[i], bg[j], acc[i][j]);
        }
        #pragma unroll
        for (int i = 0; i < 2; i++)
            #pragma unroll
            for (int j = 0; j < 2; j++)
                wmma::store_matrix_sync(Ms + (size_t)kg * 64 * 68
                                           + (qr*32 + i*16) * 68 + qc*32 + j*16,
                                        acc[i][j], 68, wmma::mem_row_major);
    }
    __syncthreads();

    // ---- reduce the two K-halves, scale by 1/64, convert to bf16 ----
    #pragma unroll
    for (int t = tid; t < 4096; t += 256) {
        int r = t >> 6, c = t & 63;
        float s = Ms[r * 68 + c] + Ms[64 * 68 + r * 68 + c];
        Msh[r * 72 + c] = __float2bfloat16(s * (1.0f / DKd));
    }
    __syncthreads();

    // ---- phase 2: Wp[c, h*64+d] = sum_e Wo[c, h*64+e] * M~[d, e] ----
    // warp owns c-rows [warp*32, warp*32+32); acc 2x4 frags (32 x 64)
    {
        wmma::fragment<wmma::accumulator,16,16,16,float> acc[2][4];
        #pragma unroll
        for (int i = 0; i < 2; i++)
            #pragma unroll
            for (int j = 0; j < 4; j++) wmma::fill_fragment(acc[i][j], 0.0f);

        #pragma unroll
        for (int kt = 0; kt < 4; kt++) {     // e blocks
            wmma::fragment<wmma::matrix_a,16,16,16,bf16,wmma::row_major> af[2];
            wmma::fragment<wmma::matrix_b,16,16,16,bf16,wmma::col_major> bg[4];
            #pragma unroll
            for (int i = 0; i < 2; i++)
                wmma::load_matrix_sync(af[i],
                    g_Wo + (size_t)(warp*32 + i*16) * ODd + h * DKd + kt*16, ODd);
            #pragma unroll
            for (int j = 0; j < 4; j++)   // B(e,d) = M~[d,e] -> col_major ldm 72
                wmma::load_matrix_sync(bg[j], Msh + (j*16) * 72 + kt*16, 72);
            #pragma unroll
            for (int i = 0; i < 2; i++)
                #pragma unroll
                for (int j = 0; j < 4; j++)
                    wmma::mma_sync(acc[i][j], af[i], bg[j], acc[i][j]);
        }
        #pragma unroll
        for (int i = 0; i < 2; i++)
            #pragma unroll
            for (int j = 0; j < 4; j++)
                wmma::store_matrix_sync(Cs + (size_t)(warp*32 + i*16) * 68 + j*16,
                                        acc[i][j], 68, wmma::mem_row_major);
    }
    __syncthreads();

    // ---- write Wp slice (256 x 64 bf16) ----
    bf16* Wpb = g_Wp + (size_t)b * CQd * ODd;
    #pragma unroll
    for (int t = tid; t < 4096; t += 256) {
        int r = t >> 4, c4 = (t & 15) * 4;
        float4 v = *(float4*)&Cs[r * 68 + c4];
        __nv_bfloat162 two[2] = { __floats2bfloat162_rn(v.x, v.y),
                                  __floats2bfloat162_rn(v.z, v.w) };
        *(uint2*)&Wpb[(size_t)r * ODd + h * DKd + c4] = *(uint2*)two;
    }
}

// ---------------------------------------------------------------------------
extern "C" void kernel_launch(void* const* d_in, const int* in_sizes, int n_in,
                              void* d_out, int out_size) {
    const float* xq    = (const float*)d_in[0];
    const float* xkv   = (const float*)d_in[1];
    const float* Wq    = (const float*)d_in[2];
    const float* Wk    = (const float*)d_in[3];
    const float* Wv    = (const float*)d_in[4];
    const float* Wo    = (const float*)d_in[5];
    const float* gamma = (const float*)d_in[6];
    float* out = (float*)d_out;

    cudaFuncSetAttribute(proj_kernel,   cudaFuncAttributeMaxDynamicSharedMemorySize, 71680);
    cudaFuncSetAttribute(final_kernel,  cudaFuncAttributeMaxDynamicSharedMemorySize, 71680);
    cudaFuncSetAttribute(kvfuse_kernel, cudaFuncAttributeMaxDynamicSharedMemorySize, 78848);

    // 1) convert everything to bf16 (one launch)
    convert_all_kernel<<<4608, 256>>>(xq, xkv, Wq, Wk, Wv, Wo);

    // 2) Q/K/V projections (one launch, z = b*3 + which)
    ProjArgs pa;
    void *p;
    cudaGetSymbolAddress(&p, g_Wq);  pa.W[0] = (const bf16*)p;
    cudaGetSymbolAddress(&p, g_Wk);  pa.W[1] = (const bf16*)p;
    cudaGetSymbolAddress(&p, g_Wv);  pa.W[2] = (const bf16*)p;
    cudaGetSymbolAddress(&p, g_xq);  pa.X[0] = (const bf16*)p;
    cudaGetSymbolAddress(&p, g_xkv); pa.X[1] = (const bf16*)p;
    cudaGetSymbolAddress(&p, g_Q);   pa.Y[0] = (bf16*)p;
    cudaGetSymbolAddress(&p, g_K);   pa.Y[1] = (bf16*)p;
    cudaGetSymbolAddress(&p, g_V);   pa.Y[2] = (bf16*)p;
    proj_kernel<<<dim3(NQd/128, ODd/128, BATCH*3), 256, 71680>>>(pa);

    // 3) fused M = (K^T V)/dk  +  Wp = Wo @ blockdiag(M^T)
    kvfuse_kernel<<<dim3(NH, BATCH), 256, 78848>>>();

    // 4) out = gamma * (Wp_b @ Q_b) + x_q
    final_kernel<<<dim3(NQd/128, CQd/128, BATCH), 256, 71680>>>(xq, gamma, out);
}